// round 2
// baseline (speedup 1.0000x reference)
#include <cuda_runtime.h>
#include <math.h>

// Problem constants (shapes fixed by the dataset)
#define H    512
#define Bm   64
#define T    256
#define BH   (Bm * H)
#define NBLK 128          // blocks per GEMM kernel: 512 units / 4 per block
#define NTHR 256
#define UNITS 4           // hidden units owned per block (16 gate columns)

#define KTOT 1024         // concat K for LSTM gates ([x | h_prev])
#define KC   64           // K chunk staged in SMEM
#define NCHUNK (KTOT / KC)

#define KB   512          // bayes K
#define KC2  128          // bayes K chunk

// ---------------- persistent device scratch (no allocations allowed) ----------------
__device__ __align__(16) float g_x[BH];        // x_t (bayes output, layer0 input)
__device__ __align__(16) float g_h0[2][BH];    // ping-pong h of layer 0
__device__ __align__(16) float g_h1[2][BH];    // ping-pong h of layer 1
__device__ __align__(16) float g_c0[BH];
__device__ __align__(16) float g_c1[BH];
__device__ __align__(16) float g_wsig[H * H];  // exp(0.5*w_log_var)
__device__ __align__(16) float g_bsig[H];

// ---------------- one-time per-launch init ----------------
__global__ void init_kernel(const float* __restrict__ init_h,
                            const float* __restrict__ init_c,
                            const float* __restrict__ wlv,
                            const float* __restrict__ blv) {
    int i = blockIdx.x * blockDim.x + threadIdx.x;
    if (i < H * H) g_wsig[i] = expf(0.5f * wlv[i]);
    if (i < BH) {
        g_h0[0][i] = init_h[i];
        g_h1[0][i] = init_h[BH + i];
        g_c0[i]    = init_c[i];
        g_c1[i]    = init_c[BH + i];
        g_x[i]     = 0.0f;
    }
    if (i < H) g_bsig[i] = expf(0.5f * blv[i]);
}

// ---------------- fused LSTM layer step ----------------
// Block b owns hidden units u0..u0+3 of this layer. Computes the 16 gate
// columns {gate*512 + u} for its units: gates = [xin | hprev] @ Wcat^T + bias,
// then the LSTM cell update, writing h_new (ping-pong) and c (in place).
//
// GEMM: C[64][16], K=1024. 256 threads = 16 output tiles (8b x 8c) x 16-way
// K-split; deterministic width-16 shuffle reduction.
extern "C" __global__ void __launch_bounds__(NTHR, 1)
lstm_layer_kernel(int layer, int ping,
                  const float* __restrict__ Wih, const float* __restrict__ Whh,
                  const float* __restrict__ bih, const float* __restrict__ bhh,
                  float* __restrict__ out /* null for layer 0 */) {
    extern __shared__ float smem[];
    float* Ws   = smem;                  // [16][1024], row c = W row (c>>2)*512 + u0 + (c&3)
    float* Xs   = smem + 16 * 1024;      // [64][KC]
    float* bsum = Xs + Bm * KC;          // [16]
    float* sg   = Xs;                    // alias (used after K loop): [64][16]

    const float* xin;  const float* hprev;  float* hnew;  float* cst;
    if (layer == 0) { xin = g_x;            hprev = g_h0[ping]; hnew = g_h0[ping ^ 1]; cst = g_c0; }
    else            { xin = g_h0[ping ^ 1]; hprev = g_h1[ping]; hnew = g_h1[ping ^ 1]; cst = g_c1; }

    const int tid = threadIdx.x;
    const int u0  = blockIdx.x * UNITS;

    // Stage weight slice: 16 rows x 1024 (first 512 from W_ih, rest from W_hh).
    #pragma unroll
    for (int j = 0; j < 16; j++) {
        int fi = tid + j * NTHR;             // float4 index, 4096 total
        int c  = fi >> 8;                    // 256 float4 per smem row
        int k  = (fi & 255) * 4;
        int r  = (c >> 2) * H + u0 + (c & 3);
        float4 v;
        if (k < H) v = *(const float4*)(Wih + (size_t)r * H + k);
        else       v = *(const float4*)(Whh + (size_t)r * H + (k - H));
        *(float4*)(Ws + c * 1024 + k) = v;
    }
    if (tid < 16) {
        int r = (tid >> 2) * H + u0 + (tid & 3);
        bsum[tid] = bih[r] + bhh[r];
    }

    const int ks   = tid & 15;           // K-split lane (width-16 shuffle group)
    const int tile = tid >> 4;           // 16 output tiles
    const int b0   = (tile & 7) * 8;
    const int c0   = (tile >> 3) * 8;

    float acc[8][8];
    #pragma unroll
    for (int i = 0; i < 8; i++)
        #pragma unroll
        for (int j = 0; j < 8; j++) acc[i][j] = 0.0f;

    // Software-pipelined activation staging (prefetch into regs, STS, compute).
    float4 pre[4];
    #pragma unroll
    for (int j = 0; j < 4; j++) {
        int fi = tid + j * NTHR;             // 1024 float4 per chunk
        int b  = fi >> 4;                    // 16 float4 per row
        int kq = fi & 15;
        pre[j] = *(const float4*)(xin + (size_t)b * H + kq * 4);  // chunk 0 is in xin
    }

    for (int ch = 0; ch < NCHUNK; ch++) {
        __syncthreads();                     // previous chunk reads / sg aliasing safe
        #pragma unroll
        for (int j = 0; j < 4; j++) {
            int fi = tid + j * NTHR;
            int b  = fi >> 4;
            int kq = fi & 15;
            *(float4*)(Xs + b * KC + kq * 4) = pre[j];
        }
        __syncthreads();
        if (ch + 1 < NCHUNK) {               // prefetch next chunk (overlaps compute)
            int kb = (ch + 1) * KC;
            const float* src  = (kb < H) ? xin : hprev;
            int          koff = (kb < H) ? kb : (kb - H);
            #pragma unroll
            for (int j = 0; j < 4; j++) {
                int fi = tid + j * NTHR;
                int b  = fi >> 4;
                int kq = fi & 15;
                pre[j] = *(const float4*)(src + (size_t)b * H + koff + kq * 4);
            }
        }
        // Each thread handles its 4-wide K quad of this chunk for an 8x8 tile.
        const int kk = ch * KC + ks * 4;
        float4 xv[8], wv[8];
        #pragma unroll
        for (int i = 0; i < 8; i++) xv[i] = *(const float4*)(Xs + (b0 + i) * KC + ks * 4);
        #pragma unroll
        for (int j = 0; j < 8; j++) wv[j] = *(const float4*)(Ws + (c0 + j) * 1024 + kk);
        #pragma unroll
        for (int i = 0; i < 8; i++)
            #pragma unroll
            for (int j = 0; j < 8; j++) {
                acc[i][j] += xv[i].x * wv[j].x;
                acc[i][j] += xv[i].y * wv[j].y;
                acc[i][j] += xv[i].z * wv[j].z;
                acc[i][j] += xv[i].w * wv[j].w;
            }
    }

    // Deterministic K-split reduction (width-16 shuffle), writers: ks==0.
    __syncthreads();
    #pragma unroll
    for (int i = 0; i < 8; i++)
        #pragma unroll
        for (int j = 0; j < 8; j++) {
            float v = acc[i][j];
            v += __shfl_down_sync(0xffffffffu, v, 8, 16);
            v += __shfl_down_sync(0xffffffffu, v, 4, 16);
            v += __shfl_down_sync(0xffffffffu, v, 2, 16);
            v += __shfl_down_sync(0xffffffffu, v, 1, 16);
            if (ks == 0) sg[(b0 + i) * 16 + (c0 + j)] = v;
        }
    __syncthreads();

    // LSTM cell: 256 threads = 64 batches x 4 units.
    {
        int b  = tid >> 2;
        int uu = tid & 3;
        float gi = sg[b * 16 + 0  + uu] + bsum[0  + uu];
        float gf = sg[b * 16 + 4  + uu] + bsum[4  + uu];
        float gg = sg[b * 16 + 8  + uu] + bsum[8  + uu];
        float go = sg[b * 16 + 12 + uu] + bsum[12 + uu];
        float iv = 1.0f / (1.0f + expf(-gi));
        float fv = 1.0f / (1.0f + expf(-gf));
        float gv = tanhf(gg);
        float ov = 1.0f / (1.0f + expf(-go));
        int idx = b * H + u0 + uu;
        float cn = fv * cst[idx] + iv * gv;
        cst[idx] = cn;
        float hn = ov * tanhf(cn);
        hnew[idx] = hn;
        if (out) out[idx] = hn;
    }
}

// ---------------- Bayesian linear step ----------------
// x_next[b][j] = sum_k h1[b][k] * (w_mu[j][k] + w_sigma[j][k]*ew_t[j][k]) + b_t[j]
// Block owns 4 output units. 8 warps = 8 batch tiles (8b x 4c), 32-way K-split.
extern "C" __global__ void __launch_bounds__(NTHR, 1)
bayes_kernel(int ping,
             const float* __restrict__ w_mu, const float* __restrict__ b_mu,
             const float* __restrict__ epsw, const float* __restrict__ epsb) {
    __shared__ __align__(16) float Wb[4 * KB];        // sampled weight rows
    __shared__ __align__(16) float Hs[Bm * KC2];
    __shared__ float bb[4];

    const float* h1 = g_h1[ping ^ 1];
    const int tid = threadIdx.x;
    const int j0  = blockIdx.x * 4;

    // Sample the 4 weight rows on the fly (fuses eps_w streaming with the GEMM).
    #pragma unroll
    for (int j = 0; j < 8; j++) {
        int idx = tid + j * NTHR;                     // 2048 elements
        int jl  = idx >> 9;
        int k   = idx & 511;
        size_t gi = (size_t)(j0 + jl) * H + k;
        Wb[jl * KB + k] = w_mu[gi] + g_wsig[gi] * epsw[gi];
    }
    if (tid < 4) bb[tid] = b_mu[j0 + tid] + g_bsig[j0 + tid] * epsb[j0 + tid];

    const int ks   = tid & 31;
    const int warp = tid >> 5;
    const int b0   = warp * 8;

    float acc[8][4];
    #pragma unroll
    for (int i = 0; i < 8; i++)
        #pragma unroll
        for (int j = 0; j < 4; j++) acc[i][j] = 0.0f;

    for (int ch = 0; ch < KB / KC2; ch++) {
        __syncthreads();
        #pragma unroll
        for (int j = 0; j < 8; j++) {
            int fi = tid + j * NTHR;                  // 2048 float4
            int b  = fi >> 5;                         // 32 float4 per row
            int kq = fi & 31;
            *(float4*)(Hs + b * KC2 + kq * 4) =
                *(const float4*)(h1 + (size_t)b * H + ch * KC2 + kq * 4);
        }
        __syncthreads();
        float4 hv[8], wv[4];
        #pragma unroll
        for (int i = 0; i < 8; i++) hv[i] = *(const float4*)(Hs + (b0 + i) * KC2 + ks * 4);
        #pragma unroll
        for (int j = 0; j < 4; j++) wv[j] = *(const float4*)(Wb + j * KB + ch * KC2 + ks * 4);
        #pragma unroll
        for (int i = 0; i < 8; i++)
            #pragma unroll
            for (int j = 0; j < 4; j++) {
                acc[i][j] += hv[i].x * wv[j].x;
                acc[i][j] += hv[i].y * wv[j].y;
                acc[i][j] += hv[i].z * wv[j].z;
                acc[i][j] += hv[i].w * wv[j].w;
            }
    }

    // Deterministic full-warp reduction; lane 0 writes.
    #pragma unroll
    for (int i = 0; i < 8; i++)
        #pragma unroll
        for (int j = 0; j < 4; j++) {
            float v = acc[i][j];
            v += __shfl_down_sync(0xffffffffu, v, 16);
            v += __shfl_down_sync(0xffffffffu, v, 8);
            v += __shfl_down_sync(0xffffffffu, v, 4);
            v += __shfl_down_sync(0xffffffffu, v, 2);
            v += __shfl_down_sync(0xffffffffu, v, 1);
            if (ks == 0) g_x[(b0 + i) * H + j0 + j] = v + bb[j];
        }
}

// ---------------- launcher ----------------
extern "C" void kernel_launch(void* const* d_in, const int* in_sizes, int n_in,
                              void* d_out, int out_size) {
    // metadata order: seq_len, init_h, init_c, eps_w, eps_b,
    //                 W_ih0, W_hh0, b_ih0, b_hh0, W_ih1, W_hh1, b_ih1, b_hh1,
    //                 w_mu, w_log_var, b_mu, b_log_var
    const float* init_h = (const float*)d_in[1];
    const float* init_c = (const float*)d_in[2];
    const float* eps_w  = (const float*)d_in[3];
    const float* eps_b  = (const float*)d_in[4];
    const float* W_ih0  = (const float*)d_in[5];
    const float* W_hh0  = (const float*)d_in[6];
    const float* b_ih0  = (const float*)d_in[7];
    const float* b_hh0  = (const float*)d_in[8];
    const float* W_ih1  = (const float*)d_in[9];
    const float* W_hh1  = (const float*)d_in[10];
    const float* b_ih1  = (const float*)d_in[11];
    const float* b_hh1  = (const float*)d_in[12];
    const float* w_mu   = (const float*)d_in[13];
    const float* w_lv   = (const float*)d_in[14];
    const float* b_mu   = (const float*)d_in[15];
    const float* b_lv   = (const float*)d_in[16];
    float* out = (float*)d_out;

    const size_t smem_ab = (size_t)(16 * 1024 + Bm * KC + 16) * sizeof(float); // ~80 KB
    cudaFuncSetAttribute((const void*)lstm_layer_kernel,
                         cudaFuncAttributeMaxDynamicSharedMemorySize, (int)smem_ab);

    init_kernel<<<(H * H + NTHR - 1) / NTHR, NTHR>>>(init_h, init_c, w_lv, b_lv);

    for (int t = 0; t < T; t++) {
        int ping = t & 1;
        lstm_layer_kernel<<<NBLK, NTHR, smem_ab>>>(0, ping, W_ih0, W_hh0, b_ih0, b_hh0,
                                                   (float*)nullptr);
        lstm_layer_kernel<<<NBLK, NTHR, smem_ab>>>(1, ping, W_ih1, W_hh1, b_ih1, b_hh1,
                                                   out + (size_t)t * BH);
        bayes_kernel<<<NBLK, NTHR>>>(ping, w_mu, b_mu,
                                     eps_w + (size_t)t * H * H,
                                     eps_b + (size_t)t * H);
    }
}

// round 4
// speedup vs baseline: 1.1739x; 1.1739x over previous
#include <cuda_runtime.h>
#include <math.h>

// Shapes fixed by the dataset
#define H    512
#define Bm   64
#define T    256
#define BH   (Bm * H)
#define NBLK 128          // persistent blocks, 1 per SM (<=148 SMs), all resident
#define NTHR 256
#define KC   64           // LSTM K chunk staged in SMEM
#define NCHUNK 16         // 1024 / 64
#define KC2  128          // bayes K chunk

// ---- persistent device state (no allocations allowed) ----
__device__ unsigned g_bar;
__device__ __align__(16) float g_x[BH];        // bayes output -> layer0 input
__device__ __align__(16) float g_h0[2][BH];    // ping-pong h layer 0
__device__ __align__(16) float g_h1[2][BH];    // ping-pong h layer 1

// ---- SMEM layout (float offsets) ----
#define OFF_W0   0          // [16][1024] layer0 weight slice
#define OFF_W1   16384      // [16][1024] layer1 weight slice
#define OFF_MU   32768      // [4][512] bayes w_mu rows
#define OFF_SIG  34816      // [4][512] bayes w_sigma rows
#define OFF_WB   36864      // [4][512] sampled bayes rows (per step)
#define OFF_ACT  38912      // 8192 floats: LSTM Xs [64][64] / bayes Hs [64][128]
#define OFF_SG   47104      // [64][16] gate scratch
#define OFF_BS0  48128      // [16]
#define OFF_BS1  48144      // [16]
#define OFF_BMU  48160      // [4]
#define OFF_BSG  48164      // [4]
#define OFF_BB   48168      // [4]
#define SMEM_FLOATS 48176
#define SMEM_BYTES  (SMEM_FLOATS * 4)

// Packed fp32x2 FMA (SASS FFMA2): d(lo,hi) += a(lo,hi)*b(lo,hi).
// Packing is along K (even/odd K in one b64) so operands come straight from
// 16B shared loads of the existing layouts — zero pack instructions.
#define FMA2(d, a, b) asm("fma.rn.f32x2 %0, %1, %2, %0;" : "+l"(d) : "l"(a), "l"(b))

__device__ __forceinline__ float fsum2(unsigned long long v) {
    float lo, hi;
    asm("mov.b64 {%0, %1}, %2;" : "=f"(lo), "=f"(hi) : "l"(v));
    return lo + hi;
}

__global__ void reset_kernel() { g_bar = 0u; }

// Monotonic grid barrier: counter never resets within a launch; target grows
// by NBLK each use. reset_kernel zeroes it at the start of every launch/replay.
__device__ __forceinline__ void grid_bar(unsigned target) {
    __syncthreads();                       // all block threads done with phase
    if (threadIdx.x == 0) {
        __threadfence();                   // release our writes to gpu scope
        atomicAdd(&g_bar, 1u);
        volatile unsigned* vb = &g_bar;
        while (*vb < target) __nanosleep(32);
        __threadfence();                   // acquire
    }
    __syncthreads();
}

// One LSTM layer step for this block's 4 hidden units.
// gates[64][16] = [xin | hprev] @ Ws^T; 16-way K-split, 8x8 reg tiles, FFMA2.
__device__ __forceinline__ void lstm_phase(
    const float* __restrict__ Ws, const float* __restrict__ bsum,
    float* __restrict__ Xs, float* __restrict__ sg,
    const float* __restrict__ xin, const float* __restrict__ hprev,
    float& cr, float* __restrict__ hnew, float* __restrict__ outp, int u0)
{
    const int tid  = threadIdx.x;
    const int ks   = tid & 15;
    const int tile = tid >> 4;
    const int b0   = (tile & 7) * 8;
    const int c0   = (tile >> 3) * 8;

    unsigned long long acc[8][8];
    #pragma unroll
    for (int i = 0; i < 8; i++)
        #pragma unroll
        for (int j = 0; j < 8; j++) acc[i][j] = 0ull;

    // Pipelined activation staging; cross-block data read with .cg (L2 coherent).
    float4 pre[4];
    #pragma unroll
    for (int j = 0; j < 4; j++) {
        int fi = tid + j * NTHR;
        int b = fi >> 4, kq = fi & 15;
        pre[j] = __ldcg((const float4*)(xin + b * H + kq * 4));
    }

    for (int ch = 0; ch < NCHUNK; ch++) {
        __syncthreads();
        #pragma unroll
        for (int j = 0; j < 4; j++) {
            int fi = tid + j * NTHR;
            int b = fi >> 4, kq = fi & 15;
            *(float4*)(Xs + b * KC + kq * 4) = pre[j];
        }
        __syncthreads();
        if (ch + 1 < NCHUNK) {
            int kb = (ch + 1) * KC;
            const float* src  = (kb < H) ? xin : hprev;
            int          koff = (kb < H) ? kb : kb - H;
            #pragma unroll
            for (int j = 0; j < 4; j++) {
                int fi = tid + j * NTHR;
                int b = fi >> 4, kq = fi & 15;
                pre[j] = __ldcg((const float4*)(src + b * H + koff + kq * 4));
            }
        }
        ulonglong2 xv[8];
        #pragma unroll
        for (int i = 0; i < 8; i++)
            xv[i] = *(const ulonglong2*)(Xs + (b0 + i) * KC + ks * 4);
        // Load one weight column at a time to keep live registers low
        // (acc is already 128 regs as b64).
        #pragma unroll
        for (int j = 0; j < 8; j++) {
            ulonglong2 wv = *(const ulonglong2*)(Ws + (c0 + j) * 1024 + ch * KC + ks * 4);
            #pragma unroll
            for (int i = 0; i < 8; i++) {
                FMA2(acc[i][j], xv[i].x, wv.x);
                FMA2(acc[i][j], xv[i].y, wv.y);
            }
        }
    }

    __syncthreads();
    #pragma unroll
    for (int i = 0; i < 8; i++)
        #pragma unroll
        for (int j = 0; j < 8; j++) {
            float v = fsum2(acc[i][j]);
            v += __shfl_down_sync(0xffffffffu, v, 8, 16);
            v += __shfl_down_sync(0xffffffffu, v, 4, 16);
            v += __shfl_down_sync(0xffffffffu, v, 2, 16);
            v += __shfl_down_sync(0xffffffffu, v, 1, 16);
            if (ks == 0) sg[(b0 + i) * 16 + (c0 + j)] = v;
        }
    __syncthreads();

    // Cell update: thread -> (batch, unit); c lives in a register all sequence.
    {
        int b = tid >> 2, uu = tid & 3;
        float gi = sg[b * 16 + 0  + uu] + bsum[0  + uu];
        float gf = sg[b * 16 + 4  + uu] + bsum[4  + uu];
        float gg = sg[b * 16 + 8  + uu] + bsum[8  + uu];
        float go = sg[b * 16 + 12 + uu] + bsum[12 + uu];
        float iv = 1.0f / (1.0f + expf(-gi));
        float fv = 1.0f / (1.0f + expf(-gf));
        float gv = tanhf(gg);
        float ov = 1.0f / (1.0f + expf(-go));
        int idx = b * H + u0 + uu;
        float cn = fv * cr + iv * gv;
        cr = cn;
        float hn = ov * tanhf(cn);
        hnew[idx] = hn;
        if (outp) outp[idx] = hn;
    }
}

extern "C" __global__ void __launch_bounds__(NTHR, 1)
dlstm_persistent(const float* __restrict__ init_h, const float* __restrict__ init_c,
                 const float* __restrict__ eps_w,  const float* __restrict__ eps_b,
                 const float* __restrict__ W_ih0, const float* __restrict__ W_hh0,
                 const float* __restrict__ b_ih0, const float* __restrict__ b_hh0,
                 const float* __restrict__ W_ih1, const float* __restrict__ W_hh1,
                 const float* __restrict__ b_ih1, const float* __restrict__ b_hh1,
                 const float* __restrict__ w_mu,  const float* __restrict__ w_lv,
                 const float* __restrict__ b_mu,  const float* __restrict__ b_lv,
                 float* __restrict__ out)
{
    extern __shared__ float sm[];
    float* W0s   = sm + OFF_W0;
    float* W1s   = sm + OFF_W1;
    float* mu_s  = sm + OFF_MU;
    float* sig_s = sm + OFF_SIG;
    float* Wb    = sm + OFF_WB;
    float* act   = sm + OFF_ACT;   // Xs (LSTM) / Hs (bayes)
    float* sg    = sm + OFF_SG;
    float* bsum0 = sm + OFF_BS0;
    float* bsum1 = sm + OFF_BS1;
    float* bmu_s = sm + OFF_BMU;
    float* bsg_s = sm + OFF_BSG;
    float* bb    = sm + OFF_BB;

    const int tid = threadIdx.x;
    const int u0  = blockIdx.x * 4;   // hidden-unit slice (also bayes rows j0)
    const int j0  = u0;

    // ---------------- prologue: stage everything resident ----------------
    #pragma unroll
    for (int j = 0; j < 16; j++) {
        int fi = tid + j * NTHR;          // 4096 float4 per weight array
        int c  = fi >> 8;
        int k  = (fi & 255) * 4;
        int r  = (c >> 2) * H + u0 + (c & 3);
        float4 v0 = (k < H) ? __ldg((const float4*)(W_ih0 + (size_t)r * H + k))
                            : __ldg((const float4*)(W_hh0 + (size_t)r * H + (k - H)));
        *(float4*)(W0s + c * 1024 + k) = v0;
        float4 v1 = (k < H) ? __ldg((const float4*)(W_ih1 + (size_t)r * H + k))
                            : __ldg((const float4*)(W_hh1 + (size_t)r * H + (k - H)));
        *(float4*)(W1s + c * 1024 + k) = v1;
    }
    #pragma unroll
    for (int r = 0; r < 2; r++) {
        int idx = tid * 8 + r * 4;        // linear over [4][512]
        int jl  = idx >> 9, k = idx & 511;
        float4 m = __ldg((const float4*)(w_mu + (size_t)(j0 + jl) * H + k));
        float4 l = __ldg((const float4*)(w_lv + (size_t)(j0 + jl) * H + k));
        float4 s;
        s.x = expf(0.5f * l.x); s.y = expf(0.5f * l.y);
        s.z = expf(0.5f * l.z); s.w = expf(0.5f * l.w);
        *(float4*)(mu_s + idx)  = m;
        *(float4*)(sig_s + idx) = s;
    }
    if (tid < 16) {
        int r = (tid >> 2) * H + u0 + (tid & 3);
        bsum0[tid] = b_ih0[r] + b_hh0[r];
        bsum1[tid] = b_ih1[r] + b_hh1[r];
    }
    if (tid < 4) {
        bmu_s[tid] = b_mu[j0 + tid];
        bsg_s[tid] = expf(0.5f * b_lv[j0 + tid]);
    }
    // state: c in registers; h slices to global; x zeroed (128*256 == BH)
    float c0r, c1r;
    {
        int b = tid >> 2, uu = tid & 3;
        int hidx = b * H + u0 + uu;
        c0r = init_c[hidx];
        c1r = init_c[BH + hidx];
        g_h0[0][hidx] = init_h[hidx];
        g_h1[0][hidx] = init_h[BH + hidx];
        g_x[blockIdx.x * NTHR + tid] = 0.0f;
    }
    unsigned tgt = NBLK;
    grid_bar(tgt);

    // ---------------- time loop ----------------
    for (int t = 0; t < T; t++) {
        const int ping = t & 1;
        const float* h0p = g_h0[ping];
        float*       h0n = g_h0[ping ^ 1];
        const float* h1p = g_h1[ping];
        float*       h1n = g_h1[ping ^ 1];

        // Phase A: layer 0
        lstm_phase(W0s, bsum0, act, sg, g_x, h0p, c0r, h0n, (float*)0, u0);
        tgt += NBLK; grid_bar(tgt);

        // Prefetch this step's eps (consumed in phase C; latency hidden by B)
        float4 er[2]; float ebr = 0.0f;
        {
            const float* ew = eps_w + (size_t)t * H * H;
            #pragma unroll
            for (int r = 0; r < 2; r++) {
                int idx = tid * 8 + r * 4;
                int jl  = idx >> 9, k = idx & 511;
                er[r] = __ldcs((const float4*)(ew + (size_t)(j0 + jl) * H + k));
            }
            if (tid < 4) ebr = __ldcs(eps_b + (size_t)t * H + j0 + tid);
        }

        // Phase B: layer 1 (also writes the timestep output)
        lstm_phase(W1s, bsum1, act, sg, h0n, h1p, c1r, h1n,
                   out + (size_t)t * BH, u0);
        tgt += NBLK; grid_bar(tgt);

        // Phase C: bayes x_next = h1 @ (mu + sig*eps)^T + b_t
        {
            #pragma unroll
            for (int r = 0; r < 2; r++) {
                int idx = tid * 8 + r * 4;
                float4 m = *(const float4*)(mu_s + idx);
                float4 s = *(const float4*)(sig_s + idx);
                float4 e = er[r];
                float4 w;
                w.x = m.x + s.x * e.x; w.y = m.y + s.y * e.y;
                w.z = m.z + s.z * e.z; w.w = m.w + s.w * e.w;
                *(float4*)(Wb + idx) = w;
            }
            if (tid < 4) bb[tid] = bmu_s[tid] + bsg_s[tid] * ebr;

            const int ks = tid & 31;
            const int b0 = (tid >> 5) * 8;
            unsigned long long acc[8][4];
            #pragma unroll
            for (int i = 0; i < 8; i++)
                #pragma unroll
                for (int j = 0; j < 4; j++) acc[i][j] = 0ull;

            for (int ch = 0; ch < 4; ch++) {
                __syncthreads();
                #pragma unroll
                for (int j = 0; j < 8; j++) {
                    int fi = tid + j * NTHR;
                    int b = fi >> 5, kq = fi & 31;
                    *(float4*)(act + b * KC2 + kq * 4) =
                        __ldcg((const float4*)(h1n + b * H + ch * KC2 + kq * 4));
                }
                __syncthreads();
                ulonglong2 hv[8];
                #pragma unroll
                for (int i = 0; i < 8; i++)
                    hv[i] = *(const ulonglong2*)(act + (b0 + i) * KC2 + ks * 4);
                #pragma unroll
                for (int j = 0; j < 4; j++) {
                    ulonglong2 wv = *(const ulonglong2*)(Wb + j * H + ch * KC2 + ks * 4);
                    #pragma unroll
                    for (int i = 0; i < 8; i++) {
                        FMA2(acc[i][j], hv[i].x, wv.x);
                        FMA2(acc[i][j], hv[i].y, wv.y);
                    }
                }
            }
            #pragma unroll
            for (int i = 0; i < 8; i++)
                #pragma unroll
                for (int j = 0; j < 4; j++) {
                    float v = fsum2(acc[i][j]);
                    v += __shfl_down_sync(0xffffffffu, v, 16);
                    v += __shfl_down_sync(0xffffffffu, v, 8);
                    v += __shfl_down_sync(0xffffffffu, v, 4);
                    v += __shfl_down_sync(0xffffffffu, v, 2);
                    v += __shfl_down_sync(0xffffffffu, v, 1);
                    if (ks == 0) g_x[(b0 + i) * H + j0 + j] = v + bb[j];
                }
        }
        tgt += NBLK; grid_bar(tgt);
    }
}

// ---------------- launcher ----------------
extern "C" void kernel_launch(void* const* d_in, const int* in_sizes, int n_in,
                              void* d_out, int out_size) {
    // metadata order: seq_len, init_h, init_c, eps_w, eps_b,
    //                 W_ih0, W_hh0, b_ih0, b_hh0, W_ih1, W_hh1, b_ih1, b_hh1,
    //                 w_mu, w_log_var, b_mu, b_log_var
    const float* init_h = (const float*)d_in[1];
    const float* init_c = (const float*)d_in[2];
    const float* eps_w  = (const float*)d_in[3];
    const float* eps_b  = (const float*)d_in[4];
    const float* W_ih0  = (const float*)d_in[5];
    const float* W_hh0  = (const float*)d_in[6];
    const float* b_ih0  = (const float*)d_in[7];
    const float* b_hh0  = (const float*)d_in[8];
    const float* W_ih1  = (const float*)d_in[9];
    const float* W_hh1  = (const float*)d_in[10];
    const float* b_ih1  = (const float*)d_in[11];
    const float* b_hh1  = (const float*)d_in[12];
    const float* w_mu   = (const float*)d_in[13];
    const float* w_lv   = (const float*)d_in[14];
    const float* b_mu   = (const float*)d_in[15];
    const float* b_lv   = (const float*)d_in[16];
    float* out = (float*)d_out;

    cudaFuncSetAttribute((const void*)dlstm_persistent,
                         cudaFuncAttributeMaxDynamicSharedMemorySize, SMEM_BYTES);

    reset_kernel<<<1, 1>>>();
    dlstm_persistent<<<NBLK, NTHR, SMEM_BYTES>>>(
        init_h, init_c, eps_w, eps_b,
        W_ih0, W_hh0, b_ih0, b_hh0,
        W_ih1, W_hh1, b_ih1, b_hh1,
        w_mu, w_lv, b_mu, b_lv, out);
}

// round 5
// speedup vs baseline: 1.2131x; 1.0334x over previous
#include <cuda_runtime.h>
#include <math.h>

// Shapes fixed by the dataset
#define H    512
#define Bm   64
#define T    256
#define BH   (Bm * H)
#define NBLK 128          // persistent blocks, 1 per SM, all resident
#define NTHR 256
#define KC   128          // LSTM K chunk staged in SMEM
#define NCHUNK 8          // 1024 / 128
#define KC2  128          // bayes K chunk

// ---- persistent device state (no allocations allowed) ----
__device__ unsigned g_bar;
__device__ __align__(16) float g_x[BH];        // bayes output -> layer0 input
__device__ __align__(16) float g_h0[2][BH];    // ping-pong h layer 0
__device__ __align__(16) float g_h1[2][BH];    // ping-pong h layer 1

// ---- SMEM layout (float offsets) ----
// Weights: pair-interleaved swizzled: Wp[8 colpairs][512 units][4 floats]
//   unit u of colpair cp holds (w[2cp][k], w[2cp+1][k], w[2cp][k+1], w[2cp+1][k+1])
//   with u = 2q + (h ^ ((q>>2)&1)), q = k>>2, h = (k&3)>>1.
#define OFF_W0   0          // 16384 floats
#define OFF_W1   16384      // 16384 floats
#define OFF_MU   32768      // [4][512] bayes w_mu rows
#define OFF_SIG  34816      // [4][512] bayes w_sigma rows
#define OFF_WB   36864      // [4][512] sampled bayes rows (per step)
#define OFF_ACT  38912      // 8192 floats: LSTM Xs [64][128] / bayes Hs [64][128]
#define OFF_SG   47104      // [64][16] gate scratch
#define OFF_BS0  48128      // [16]
#define OFF_BS1  48144      // [16]
#define OFF_BMU  48160      // [4]
#define OFF_BSG  48164      // [4]
#define OFF_BB   48168      // [4]
#define SMEM_FLOATS 48176
#define SMEM_BYTES  (SMEM_FLOATS * 4)

// Packed fp32x2 ops (SASS FFMA2/FADD2 — only reachable via PTX)
#define FMA2(d, a, b) asm("fma.rn.f32x2 %0, %1, %2, %0;" : "+l"(d) : "l"(a), "l"(b))
#define ADD2(d, a)    asm("add.rn.f32x2 %0, %0, %1;"     : "+l"(d) : "l"(a))
#define BCAST2(d, x)  asm("mov.b64 %0, {%1, %1};"        : "=l"(d) : "f"(x))

__device__ __forceinline__ void unpack2(unsigned long long v, float& lo, float& hi) {
    asm("mov.b64 {%0, %1}, %2;" : "=f"(lo), "=f"(hi) : "l"(v));
}

__global__ void reset_kernel() { g_bar = 0u; }

// Monotonic grid barrier (counter reset by reset_kernel each launch/replay).
__device__ __forceinline__ void grid_bar(unsigned target) {
    __syncthreads();
    if (threadIdx.x == 0) {
        __threadfence();
        atomicAdd(&g_bar, 1u);
        volatile unsigned* vb = &g_bar;
        while (*vb < target) __nanosleep(20);
        __threadfence();
    }
    __syncthreads();
}

// One LSTM layer step for this block's 4 hidden units.
// gates[64][16] = [xin | hprev] @ W^T. 16-way K-split, 8x8 tile per thread,
// column-pair-packed FFMA2 accumulators (acc[8][4] b64 = 64 regs).
__device__ __forceinline__ void lstm_phase(
    const float* __restrict__ Wp, const float* __restrict__ bsum,
    float* __restrict__ Xs, float* __restrict__ sg,
    const float* __restrict__ xin, const float* __restrict__ hprev,
    float& cr, float* __restrict__ hnew, float* __restrict__ outp, int u0)
{
    const int tid  = threadIdx.x;
    const int ks   = tid & 15;
    const int tile = tid >> 4;
    const int b0   = (tile & 7) * 8;
    const int c0   = (tile >> 3) * 8;     // 0 or 8
    const int cpg0 = c0 >> 1;             // colpair row base: 0 or 4
    const int s    = (ks >> 2) & 1;       // swizzle bit (constant per thread)

    unsigned long long acc[8][4];
    #pragma unroll
    for (int i = 0; i < 8; i++)
        #pragma unroll
        for (int p = 0; p < 4; p++) acc[i][p] = 0ull;

    // Prefetch chunk 0 (entirely within xin: KC=128 <= H, chunks 0-3 = xin).
    float4 pre[8];
    #pragma unroll
    for (int j = 0; j < 8; j++) {
        int fi = tid + j * NTHR;
        int b = fi >> 5, kq = fi & 31;
        pre[j] = __ldcg((const float4*)(xin + b * H + kq * 4));
    }

    for (int ch = 0; ch < NCHUNK; ch++) {
        __syncthreads();
        #pragma unroll
        for (int j = 0; j < 8; j++) {
            int fi = tid + j * NTHR;
            int b = fi >> 5, kq = fi & 31;
            *(float4*)(Xs + b * KC + kq * 4) = pre[j];
        }
        __syncthreads();
        if (ch + 1 < NCHUNK) {
            int kb = (ch + 1) * KC;                 // chunk never straddles x/h
            const float* src  = (kb < H) ? xin : hprev;
            int          koff = (kb < H) ? kb : kb - H;
            #pragma unroll
            for (int j = 0; j < 8; j++) {
                int fi = tid + j * NTHR;
                int b = fi >> 5, kq = fi & 31;
                pre[j] = __ldcg((const float4*)(src + b * H + koff + kq * 4));
            }
        }
        // Two 64-wide halves; this lane's quad: k0 = ch*128 + h2*64 + ks*4.
        #pragma unroll
        for (int h2 = 0; h2 < 2; h2++) {
            const int q  = ch * 32 + h2 * 16 + ks;
            const int uA = q * 2 + s;               // h0 unit; h1 unit = uA^1
            // Weight pairs: wA = pairs for kk={0,1}, wB = pairs for kk={2,3}.
            ulonglong2 wA[4], wB[4];
            #pragma unroll
            for (int cp = 0; cp < 4; cp++) {
                const float* base = Wp + (cpg0 + cp) * 2048;
                wA[cp] = *(const ulonglong2*)(base + uA * 4);
                wB[cp] = *(const ulonglong2*)(base + (uA ^ 1) * 4);
            }
            float4 xv[8];
            #pragma unroll
            for (int i = 0; i < 8; i++)
                xv[i] = *(const float4*)(Xs + (b0 + i) * KC + h2 * 64 + ks * 4);
            #pragma unroll
            for (int kk = 0; kk < 4; kk++) {
                #pragma unroll
                for (int i = 0; i < 8; i++) {
                    unsigned long long bc;
                    BCAST2(bc, ((const float*)&xv[i])[kk]);
                    #pragma unroll
                    for (int cp = 0; cp < 4; cp++) {
                        unsigned long long w =
                            (kk == 0) ? wA[cp].x : (kk == 1) ? wA[cp].y
                          : (kk == 2) ? wB[cp].x : wB[cp].y;
                        FMA2(acc[i][cp], bc, w);
                    }
                }
            }
        }
    }

    // K-split reduction: packed adds over width-16 shuffles. Pair halves are
    // two DIFFERENT output columns -> no cross-half sum needed.
    __syncthreads();
    #pragma unroll
    for (int i = 0; i < 8; i++)
        #pragma unroll
        for (int cp = 0; cp < 4; cp++) {
            unsigned long long v = acc[i][cp];
            unsigned long long o;
            o = __shfl_down_sync(0xffffffffu, v, 8, 16); ADD2(v, o);
            o = __shfl_down_sync(0xffffffffu, v, 4, 16); ADD2(v, o);
            o = __shfl_down_sync(0xffffffffu, v, 2, 16); ADD2(v, o);
            o = __shfl_down_sync(0xffffffffu, v, 1, 16); ADD2(v, o);
            if (ks == 0) {
                float lo, hi; unpack2(v, lo, hi);
                *(float2*)(sg + (b0 + i) * 16 + c0 + 2 * cp) = make_float2(lo, hi);
            }
        }
    __syncthreads();

    // Cell update: thread -> (batch, unit); c lives in a register all sequence.
    {
        int b = tid >> 2, uu = tid & 3;
        float gi = sg[b * 16 + 0  + uu] + bsum[0  + uu];
        float gf = sg[b * 16 + 4  + uu] + bsum[4  + uu];
        float gg = sg[b * 16 + 8  + uu] + bsum[8  + uu];
        float go = sg[b * 16 + 12 + uu] + bsum[12 + uu];
        float iv = 1.0f / (1.0f + expf(-gi));
        float fv = 1.0f / (1.0f + expf(-gf));
        float gv = tanhf(gg);
        float ov = 1.0f / (1.0f + expf(-go));
        int idx = b * H + u0 + uu;
        float cn = fv * cr + iv * gv;
        cr = cn;
        float hn = ov * tanhf(cn);
        hnew[idx] = hn;
        if (outp) outp[idx] = hn;
    }
}

extern "C" __global__ void __launch_bounds__(NTHR, 1)
dlstm_persistent(const float* __restrict__ init_h, const float* __restrict__ init_c,
                 const float* __restrict__ eps_w,  const float* __restrict__ eps_b,
                 const float* __restrict__ W_ih0, const float* __restrict__ W_hh0,
                 const float* __restrict__ b_ih0, const float* __restrict__ b_hh0,
                 const float* __restrict__ W_ih1, const float* __restrict__ W_hh1,
                 const float* __restrict__ b_ih1, const float* __restrict__ b_hh1,
                 const float* __restrict__ w_mu,  const float* __restrict__ w_lv,
                 const float* __restrict__ b_mu,  const float* __restrict__ b_lv,
                 float* __restrict__ out)
{
    extern __shared__ float sm[];
    float* W0s   = sm + OFF_W0;
    float* W1s   = sm + OFF_W1;
    float* mu_s  = sm + OFF_MU;
    float* sig_s = sm + OFF_SIG;
    float* Wb    = sm + OFF_WB;
    float* act   = sm + OFF_ACT;   // Xs (LSTM) / Hs (bayes)
    float* sg    = sm + OFF_SG;
    float* bsum0 = sm + OFF_BS0;
    float* bsum1 = sm + OFF_BS1;
    float* bmu_s = sm + OFF_BMU;
    float* bsg_s = sm + OFF_BSG;
    float* bb    = sm + OFF_BB;

    const int tid = threadIdx.x;
    const int u0  = blockIdx.x * 4;   // hidden-unit slice (also bayes rows j0)
    const int j0  = u0;

    // -------- prologue: stage everything resident --------
    // Weights into pair-interleaved swizzled layout (one-time cost).
    for (int idx = tid; idx < 16 * 1024; idx += NTHR) {
        int c = idx >> 10, k = idx & 1023;
        int r = (c >> 2) * H + u0 + (c & 3);
        float w0 = (k < H) ? W_ih0[(size_t)r * H + k] : W_hh0[(size_t)r * H + k - H];
        float w1 = (k < H) ? W_ih1[(size_t)r * H + k] : W_hh1[(size_t)r * H + k - H];
        int cp = c >> 1, pe = c & 1, q = k >> 2, kk = k & 3;
        int u = q * 2 + ((kk >> 1) ^ ((q >> 2) & 1));
        int off = cp * 2048 + u * 4 + (kk & 1) * 2 + pe;
        W0s[off] = w0;
        W1s[off] = w1;
    }
    #pragma unroll
    for (int r = 0; r < 2; r++) {
        int idx = tid * 8 + r * 4;        // linear over [4][512]
        int jl  = idx >> 9, k = idx & 511;
        float4 m = __ldg((const float4*)(w_mu + (size_t)(j0 + jl) * H + k));
        float4 l = __ldg((const float4*)(w_lv + (size_t)(j0 + jl) * H + k));
        float4 s;
        s.x = expf(0.5f * l.x); s.y = expf(0.5f * l.y);
        s.z = expf(0.5f * l.z); s.w = expf(0.5f * l.w);
        *(float4*)(mu_s + idx)  = m;
        *(float4*)(sig_s + idx) = s;
    }
    if (tid < 16) {
        int r = (tid >> 2) * H + u0 + (tid & 3);
        bsum0[tid] = b_ih0[r] + b_hh0[r];
        bsum1[tid] = b_ih1[r] + b_hh1[r];
    }
    if (tid < 4) {
        bmu_s[tid] = b_mu[j0 + tid];
        bsg_s[tid] = expf(0.5f * b_lv[j0 + tid]);
    }
    // state: c in registers; h slices to global; x zeroed (128*256 == BH)
    float c0r, c1r;
    {
        int b = tid >> 2, uu = tid & 3;
        int hidx = b * H + u0 + uu;
        c0r = init_c[hidx];
        c1r = init_c[BH + hidx];
        g_h0[0][hidx] = init_h[hidx];
        g_h1[0][hidx] = init_h[BH + hidx];
        g_x[blockIdx.x * NTHR + tid] = 0.0f;
    }
    unsigned tgt = NBLK;
    grid_bar(tgt);

    // -------- time loop --------
    for (int t = 0; t < T; t++) {
        const int ping = t & 1;
        const float* h0p = g_h0[ping];
        float*       h0n = g_h0[ping ^ 1];
        const float* h1p = g_h1[ping];
        float*       h1n = g_h1[ping ^ 1];

        // Phase A: layer 0
        lstm_phase(W0s, bsum0, act, sg, g_x, h0p, c0r, h0n, (float*)0, u0);
        tgt += NBLK; grid_bar(tgt);

        // Prefetch this step's eps (consumed in phase C; latency hidden by B)
        float4 er[2]; float ebr = 0.0f;
        {
            const float* ew = eps_w + (size_t)t * H * H;
            #pragma unroll
            for (int r = 0; r < 2; r++) {
                int idx = tid * 8 + r * 4;
                int jl  = idx >> 9, k = idx & 511;
                er[r] = __ldcs((const float4*)(ew + (size_t)(j0 + jl) * H + k));
            }
            if (tid < 4) ebr = __ldcs(eps_b + (size_t)t * H + j0 + tid);
        }

        // Phase B: layer 1 (also writes the timestep output)
        lstm_phase(W1s, bsum1, act, sg, h0n, h1p, c1r, h1n,
                   out + (size_t)t * BH, u0);
        tgt += NBLK; grid_bar(tgt);

        // Phase C: bayes x_next = h1 @ (mu + sig*eps)^T + b_t
        // K-packed FFMA2, acc[8][4] b64 (pair halves = even/odd K partials).
        {
            #pragma unroll
            for (int r = 0; r < 2; r++) {
                int idx = tid * 8 + r * 4;
                float4 m = *(const float4*)(mu_s + idx);
                float4 s = *(const float4*)(sig_s + idx);
                float4 e = er[r];
                float4 w;
                w.x = m.x + s.x * e.x; w.y = m.y + s.y * e.y;
                w.z = m.z + s.z * e.z; w.w = m.w + s.w * e.w;
                *(float4*)(Wb + idx) = w;
            }
            if (tid < 4) bb[tid] = bmu_s[tid] + bsg_s[tid] * ebr;

            const int ks = tid & 31;
            const int b0 = (tid >> 5) * 8;
            unsigned long long acc[8][4];
            #pragma unroll
            for (int i = 0; i < 8; i++)
                #pragma unroll
                for (int j = 0; j < 4; j++) acc[i][j] = 0ull;

            for (int ch = 0; ch < 4; ch++) {
                __syncthreads();
                #pragma unroll
                for (int j = 0; j < 8; j++) {
                    int fi = tid + j * NTHR;
                    int b = fi >> 5, kq = fi & 31;
                    *(float4*)(act + b * KC2 + kq * 4) =
                        __ldcg((const float4*)(h1n + b * H + ch * KC2 + kq * 4));
                }
                __syncthreads();
                ulonglong2 hv[8];
                #pragma unroll
                for (int i = 0; i < 8; i++)
                    hv[i] = *(const ulonglong2*)(act + (b0 + i) * KC2 + ks * 4);
                #pragma unroll
                for (int j = 0; j < 4; j++) {
                    ulonglong2 wv = *(const ulonglong2*)(Wb + j * H + ch * KC2 + ks * 4);
                    #pragma unroll
                    for (int i = 0; i < 8; i++) {
                        FMA2(acc[i][j], hv[i].x, wv.x);
                        FMA2(acc[i][j], hv[i].y, wv.y);
                    }
                }
            }
            #pragma unroll
            for (int i = 0; i < 8; i++)
                #pragma unroll
                for (int j = 0; j < 4; j++) {
                    unsigned long long v = acc[i][j];
                    unsigned long long o;
                    o = __shfl_down_sync(0xffffffffu, v, 16); ADD2(v, o);
                    o = __shfl_down_sync(0xffffffffu, v, 8);  ADD2(v, o);
                    o = __shfl_down_sync(0xffffffffu, v, 4);  ADD2(v, o);
                    o = __shfl_down_sync(0xffffffffu, v, 2);  ADD2(v, o);
                    o = __shfl_down_sync(0xffffffffu, v, 1);  ADD2(v, o);
                    if (ks == 0) {
                        float lo, hi; unpack2(v, lo, hi);
                        g_x[(b0 + i) * H + j0 + j] = lo + hi + bb[j];
                    }
                }
        }
        tgt += NBLK; grid_bar(tgt);
    }
}

// ---------------- launcher ----------------
extern "C" void kernel_launch(void* const* d_in, const int* in_sizes, int n_in,
                              void* d_out, int out_size) {
    // metadata order: seq_len, init_h, init_c, eps_w, eps_b,
    //                 W_ih0, W_hh0, b_ih0, b_hh0, W_ih1, W_hh1, b_ih1, b_hh1,
    //                 w_mu, w_log_var, b_mu, b_log_var
    const float* init_h = (const float*)d_in[1];
    const float* init_c = (const float*)d_in[2];
    const float* eps_w  = (const float*)d_in[3];
    const float* eps_b  = (const float*)d_in[4];
    const float* W_ih0  = (const float*)d_in[5];
    const float* W_hh0  = (const float*)d_in[6];
    const float* b_ih0  = (const float*)d_in[7];
    const float* b_hh0  = (const float*)d_in[8];
    const float* W_ih1  = (const float*)d_in[9];
    const float* W_hh1  = (const float*)d_in[10];
    const float* b_ih1  = (const float*)d_in[11];
    const float* b_hh1  = (const float*)d_in[12];
    const float* w_mu   = (const float*)d_in[13];
    const float* w_lv   = (const float*)d_in[14];
    const float* b_mu   = (const float*)d_in[15];
    const float* b_lv   = (const float*)d_in[16];
    float* out = (float*)d_out;

    cudaFuncSetAttribute((const void*)dlstm_persistent,
                         cudaFuncAttributeMaxDynamicSharedMemorySize, SMEM_BYTES);

    reset_kernel<<<1, 1>>>();
    dlstm_persistent<<<NBLK, NTHR, SMEM_BYTES>>>(
        init_h, init_c, eps_w, eps_b,
        W_ih0, W_hh0, b_ih0, b_hh0,
        W_ih1, W_hh1, b_ih1, b_hh1,
        w_mu, w_lv, b_mu, b_lv, out);
}

// round 10
// speedup vs baseline: 1.3817x; 1.1390x over previous
#include <cuda_runtime.h>
#include <cuda_bf16.h>
#include <math.h>
#include <stdint.h>

// Shapes fixed by the dataset
#define H    512
#define Bm   64
#define T    256
#define BH   (Bm * H)
#define NBLK 128          // persistent blocks, 1/SM
#define NTHR 256

// ---- SMEM byte offsets ----
// Bfrag: weight fragments [layer2][pass2][ks64][nt2][lane32][reg2] b32 = 128KB
#define OFF_BF   0
// Afrag/Cp/Hs shared scratch, 32KB:
//   Afrag [pass2][ks8][mt4][r4][slot32] b32   (LSTM staging, per 128-K chunk)
//   Cp    [w8][b64][n16] f32                  (cross-warp reduction)
//   Hs    [b64][k128] f32                     (bayes activation chunk)
#define OFF_ACT  131072
#define OFF_MU   163840      // [4][512] f32 bayes mu rows (8KB)
#define OFF_SIG  172032      // (8KB)
#define OFF_WB   180224      // (8KB)
#define OFF_BS0  188416      // [16] f32
#define OFF_BS1  188480
#define OFF_BMU  188544
#define OFF_BSG  188560
#define OFF_BB   188576
#define SMEM_BYTES 188672

// ---- persistent device state (no allocations allowed) ----
__device__ unsigned g_bar;
__device__ volatile unsigned g_dead;   // watchdog
__device__ __align__(16) __nv_bfloat16 g_xhi[BH], g_xlo[BH];       // bayes out
__device__ __align__(16) __nv_bfloat16 g_h0hi[2][BH], g_h0lo[2][BH];
__device__ __align__(16) __nv_bfloat16 g_h1hi[2][BH], g_h1lo[2][BH];

// m16n8k16 bf16 mma, fp32 accumulate (sm_80+ baseline — OK on plain sm_100)
#define MMA16816(c, a, b)                                                        \
    asm volatile("mma.sync.aligned.m16n8k16.row.col.f32.bf16.bf16.f32 "          \
        "{%0,%1,%2,%3}, {%4,%5,%6,%7}, {%8,%9}, {%0,%1,%2,%3};"                  \
        : "+f"((c)[0]), "+f"((c)[1]), "+f"((c)[2]), "+f"((c)[3])                 \
        : "r"((a)[0]), "r"((a)[1]), "r"((a)[2]), "r"((a)[3]),                    \
          "r"((b)[0]), "r"((b)[1]))

// Packed fp32x2 ops for the bayes phase
#define FMA2(d, a, b) asm("fma.rn.f32x2 %0, %1, %2, %0;" : "+l"(d) : "l"(a), "l"(b))
#define ADD2(d, a)    asm("add.rn.f32x2 %0, %0, %1;"     : "+l"(d) : "l"(a))
__device__ __forceinline__ void unpack2(unsigned long long v, float& lo, float& hi) {
    asm("mov.b64 {%0, %1}, %2;" : "=f"(lo), "=f"(hi) : "l"(v));
}

__global__ void reset_kernel() { g_bar = 0u; g_dead = 0u; }

// Bounded grid barrier (watchdog converts any wedge into fast termination).
__device__ __forceinline__ void grid_bar(unsigned target) {
    __syncthreads();
    if (threadIdx.x == 0) {
        __threadfence();
        atomicAdd(&g_bar, 1u);
        volatile unsigned* vb = &g_bar;
        unsigned spin = 0;
        while (*vb < target && !g_dead) {
            __nanosleep(20);
            if (++spin > 4000000u) { g_dead = 1u; break; }
        }
        __threadfence();
    }
    __syncthreads();
}

__device__ __forceinline__ void split_store(float v, __nv_bfloat16* hi, __nv_bfloat16* lo) {
    __nv_bfloat16 h = __float2bfloat16(v);
    *hi = h;
    *lo = __float2bfloat16(v - __bfloat162float(h));
}

// ---- one LSTM layer phase via mma.sync ----
// gates C[64 batch][16 gatecols] = [xin | hprev] @ W^T, K=1024 in 8 chunks of 128.
// Warp w owns kstep w (16 K) of each chunk. 3-pass bf16 hi/lo split.
// Afrag slots XOR-swizzled by ks so staging STS and compute LDS are both
// conflict-free. Global loads double-buffered in registers.
__device__ __forceinline__ void lstm_phase_mma(
    char* smem, int layer,
    const __nv_bfloat16* __restrict__ xin_hi, const __nv_bfloat16* __restrict__ xin_lo,
    const __nv_bfloat16* __restrict__ hp_hi,  const __nv_bfloat16* __restrict__ hp_lo,
    const float* __restrict__ bsum, float& cr,
    __nv_bfloat16* __restrict__ hn_hi, __nv_bfloat16* __restrict__ hn_lo,
    float* __restrict__ out_t, int u0)
{
    const int tid  = threadIdx.x;
    const int w    = tid >> 5;      // warp id = kstep within chunk
    const int lane = tid & 31;
    uint32_t* af = (uint32_t*)(smem + OFF_ACT);
    const uint32_t* bfb = (const uint32_t*)(smem + OFF_BF);

    float acc[4][2][4];
    #pragma unroll
    for (int mt = 0; mt < 4; mt++)
        #pragma unroll
        for (int nt = 0; nt < 2; nt++)
            #pragma unroll
            for (int r = 0; r < 4; r++) acc[mt][nt][r] = 0.0f;

    // prefetch chunk 0 (always within xin)
    uint4 pr0[4], pr1[4];
    #pragma unroll
    for (int i = 0; i < 4; i++) {
        int job = tid + i * NTHR, pass = job >> 9, rem = job & 511;
        int b = rem >> 3, ks = rem & 7;
        const __nv_bfloat16* s = pass ? xin_lo : xin_hi;
        const __nv_bfloat16* p = s + (size_t)b * H + ks * 16;
        pr0[i] = __ldcg((const uint4*)p);
        pr1[i] = __ldcg((const uint4*)(p + 8));
    }

    for (int ck = 0; ck < 8; ck++) {
        __syncthreads();      // previous chunk's fragments fully consumed
        // ---- store prefetched chunk into fragment order (XOR slot swizzle) ----
        #pragma unroll
        for (int i = 0; i < 4; i++) {
            int job = tid + i * NTHR, pass = job >> 9, rem = job & 511;
            int b = rem >> 3, ks = rem & 7;
            int mt = b >> 4, g = b & 7, rb = (b >> 3) & 1;
            uint32_t base = ((uint32_t)(pass * 8 + ks) * 4 + mt) * 128
                          + (uint32_t)(((g ^ ks) & 7) * 4);
            *(uint4*)(af + base + rb * 32)       = pr0[i];   // k-lo plane
            *(uint4*)(af + base + (rb + 2) * 32) = pr1[i];   // k-hi plane
        }
        __syncthreads();
        // ---- prefetch next chunk (LDG latency overlaps compute below) ----
        if (ck + 1 < 8) {
            const int koff = (ck + 1) * 128 - ((ck + 1 >= 4) ? H : 0);
            const __nv_bfloat16* shi = (ck + 1 < 4) ? xin_hi : hp_hi;
            const __nv_bfloat16* slo = (ck + 1 < 4) ? xin_lo : hp_lo;
            #pragma unroll
            for (int i = 0; i < 4; i++) {
                int job = tid + i * NTHR, pass = job >> 9, rem = job & 511;
                int b = rem >> 3, ks = rem & 7;
                const __nv_bfloat16* s = pass ? slo : shi;
                const __nv_bfloat16* p = s + (size_t)b * H + koff + ks * 16;
                pr0[i] = __ldcg((const uint4*)p);
                pr1[i] = __ldcg((const uint4*)(p + 8));
            }
        }
        // ---- compute: warp w does kstep w of this chunk ----
        const int ksg = ck * 8 + w;            // global kstep 0..63
        const int sl = ((((lane >> 2) ^ w) & 7) * 4) + (lane & 3);
        uint32_t Ah[4][4], Al[4][4];
        #pragma unroll
        for (int mt = 0; mt < 4; mt++) {
            uint32_t bh = ((uint32_t)(0 * 8 + w) * 4 + mt) * 128 + sl;
            uint32_t bl = ((uint32_t)(1 * 8 + w) * 4 + mt) * 128 + sl;
            #pragma unroll
            for (int r = 0; r < 4; r++) {
                Ah[mt][r] = af[bh + r * 32];
                Al[mt][r] = af[bl + r * 32];
            }
        }
        uint32_t Bh[2][2], Bl[2][2];
        #pragma unroll
        for (int nt = 0; nt < 2; nt++) {
            uint32_t ih = ((((uint32_t)(layer * 2 + 0) * 64 + ksg) * 2 + nt) * 32 + lane) * 2;
            uint32_t il = ((((uint32_t)(layer * 2 + 1) * 64 + ksg) * 2 + nt) * 32 + lane) * 2;
            uint2 vh = *(const uint2*)(bfb + ih);
            uint2 vl = *(const uint2*)(bfb + il);
            Bh[nt][0] = vh.x; Bh[nt][1] = vh.y;
            Bl[nt][0] = vl.x; Bl[nt][1] = vl.y;
        }
        #pragma unroll
        for (int mt = 0; mt < 4; mt++)
            #pragma unroll
            for (int nt = 0; nt < 2; nt++) {
                MMA16816(acc[mt][nt], Ah[mt], Bh[nt]);
                MMA16816(acc[mt][nt], Ah[mt], Bl[nt]);
                MMA16816(acc[mt][nt], Al[mt], Bh[nt]);
            }
    }

    // ---- cross-warp K reduction via SMEM partials (reuses Afrag area) ----
    __syncthreads();                       // all fragment reads done
    float* cp = (float*)(smem + OFF_ACT);  // Cp[w][64][16]
    {
        int g = lane >> 2, tg = lane & 3;
        #pragma unroll
        for (int mt = 0; mt < 4; mt++)
            #pragma unroll
            for (int nt = 0; nt < 2; nt++) {
                int n0 = nt * 8 + tg * 2;
                int row = w * 64 + mt * 16 + g;
                *(float2*)(cp + row * 16 + n0) =
                    make_float2(acc[mt][nt][0], acc[mt][nt][1]);
                *(float2*)(cp + (row + 8) * 16 + n0) =
                    make_float2(acc[mt][nt][2], acc[mt][nt][3]);
            }
    }
    __syncthreads();

    // ---- cell update: thread -> (batch, unit); c in register all sequence ----
    {
        int b = tid >> 2, uu = tid & 3;
        float gsum[4];
        #pragma unroll
        for (int gate = 0; gate < 4; gate++) {
            int n = gate * 4 + uu;
            float s = 0.0f;
            #pragma unroll
            for (int ww = 0; ww < 8; ww++) s += cp[(ww * 64 + b) * 16 + n];
            gsum[gate] = s + bsum[n];
        }
        float iv = 1.0f / (1.0f + expf(-gsum[0]));
        float fv = 1.0f / (1.0f + expf(-gsum[1]));
        float gv = tanhf(gsum[2]);
        float ov = 1.0f / (1.0f + expf(-gsum[3]));
        float cn = fv * cr + iv * gv;
        cr = cn;
        float hn = ov * tanhf(cn);
        int idx = b * H + u0 + uu;
        split_store(hn, hn_hi + idx, hn_lo + idx);
        if (out_t) out_t[idx] = hn;
    }
}

extern "C" __global__ void __launch_bounds__(NTHR, 1)
dlstm_persistent(const float* __restrict__ init_h, const float* __restrict__ init_c,
                 const float* __restrict__ eps_w,  const float* __restrict__ eps_b,
                 const float* __restrict__ W_ih0, const float* __restrict__ W_hh0,
                 const float* __restrict__ b_ih0, const float* __restrict__ b_hh0,
                 const float* __restrict__ W_ih1, const float* __restrict__ W_hh1,
                 const float* __restrict__ b_ih1, const float* __restrict__ b_hh1,
                 const float* __restrict__ w_mu,  const float* __restrict__ w_lv,
                 const float* __restrict__ b_mu,  const float* __restrict__ b_lv,
                 float* __restrict__ out)
{
    extern __shared__ __align__(16) char smem[];
    const int tid = threadIdx.x;
    const int u0 = blockIdx.x * 4, j0 = u0;

    uint32_t* bfb  = (uint32_t*)(smem + OFF_BF);
    float* mu_s  = (float*)(smem + OFF_MU);
    float* sig_s = (float*)(smem + OFF_SIG);
    float* Wb    = (float*)(smem + OFF_WB);
    float* bsum0 = (float*)(smem + OFF_BS0);
    float* bsum1 = (float*)(smem + OFF_BS1);
    float* bmu_s = (float*)(smem + OFF_BMU);
    float* bsg_s = (float*)(smem + OFF_BSG);
    float* bb    = (float*)(smem + OFF_BB);
    float* Hs    = (float*)(smem + OFF_ACT);

    // ---- prologue: weight fragments (resident whole run) ----
    // idx = (layer, c 0..15, kq 0..511); B[k][n=c] = Wcat[row(c)][k], pairs (k,k+1).
    for (int idx = tid; idx < 2 * 16 * 512; idx += NTHR) {
        int l  = idx >> 13;
        int c  = (idx >> 9) & 15;
        int kq = idx & 511;
        int k  = kq * 2;
        int r  = (c >> 2) * H + u0 + (c & 3);
        const float* Wih = l ? W_ih1 : W_ih0;
        const float* Whh = l ? W_hh1 : W_hh0;
        const float* src = (k < H) ? (Wih + (size_t)r * H + k)
                                   : (Whh + (size_t)r * H + (k - H));
        float2 wv = *(const float2*)src;
        __nv_bfloat16 h0 = __float2bfloat16(wv.x);
        __nv_bfloat16 h1 = __float2bfloat16(wv.y);
        __nv_bfloat16 l0 = __float2bfloat16(wv.x - __bfloat162float(h0));
        __nv_bfloat16 l1 = __float2bfloat16(wv.y - __bfloat162float(h1));
        uint32_t hip, lop;
        asm("mov.b32 %0, {%1, %2};" : "=r"(hip) : "h"((unsigned short)__bfloat16_as_ushort(h0)),
                                                  "h"((unsigned short)__bfloat16_as_ushort(h1)));
        asm("mov.b32 %0, {%1, %2};" : "=r"(lop) : "h"((unsigned short)__bfloat16_as_ushort(l0)),
                                                  "h"((unsigned short)__bfloat16_as_ushort(l1)));
        int ksg = kq >> 3;
        int tg  = kq & 3;
        int reg = (kq >> 2) & 1;
        int nt  = c >> 3, g = c & 7;
        int lane = g * 4 + tg;
        bfb[((((uint32_t)(l * 2 + 0) * 64 + ksg) * 2 + nt) * 32 + lane) * 2 + reg] = hip;
        bfb[((((uint32_t)(l * 2 + 1) * 64 + ksg) * 2 + nt) * 32 + lane) * 2 + reg] = lop;
    }
    // bayes params
    #pragma unroll
    for (int r = 0; r < 2; r++) {
        int idx = tid * 8 + r * 4;
        int jl = idx >> 9, k = idx & 511;
        float4 m = __ldg((const float4*)(w_mu + (size_t)(j0 + jl) * H + k));
        float4 l4 = __ldg((const float4*)(w_lv + (size_t)(j0 + jl) * H + k));
        float4 s;
        s.x = expf(0.5f * l4.x); s.y = expf(0.5f * l4.y);
        s.z = expf(0.5f * l4.z); s.w = expf(0.5f * l4.w);
        *(float4*)(mu_s + idx) = m;
        *(float4*)(sig_s + idx) = s;
    }
    if (tid < 16) {
        int r = (tid >> 2) * H + u0 + (tid & 3);
        bsum0[tid] = b_ih0[r] + b_hh0[r];
        bsum1[tid] = b_ih1[r] + b_hh1[r];
    }
    if (tid < 4) {
        bmu_s[tid] = b_mu[j0 + tid];
        bsg_s[tid] = expf(0.5f * b_lv[j0 + tid]);
    }
    // state init: split h slices to global; c in per-thread registers; x = 0
    float c0r, c1r;
    {
        int b = tid >> 2, uu = tid & 3;
        int idx = b * H + u0 + uu;
        c0r = init_c[idx];
        c1r = init_c[BH + idx];
        split_store(init_h[idx],      &g_h0hi[0][idx], &g_h0lo[0][idx]);
        split_store(init_h[BH + idx], &g_h1hi[0][idx], &g_h1lo[0][idx]);
        g_xhi[blockIdx.x * NTHR + tid] = __float2bfloat16(0.0f);
        g_xlo[blockIdx.x * NTHR + tid] = __float2bfloat16(0.0f);
    }
    unsigned tgt = NBLK;
    grid_bar(tgt);

    // ---- time loop ----
    for (int t = 0; t < T; t++) {
        const int ping = t & 1, pong = ping ^ 1;

        // Phase A: layer 0
        lstm_phase_mma(smem, 0, g_xhi, g_xlo, g_h0hi[ping], g_h0lo[ping],
                       bsum0, c0r, g_h0hi[pong], g_h0lo[pong], (float*)0, u0);
        tgt += NBLK; grid_bar(tgt);

        // eps prefetch for phase C (latency hidden behind B)
        float4 er[2]; float ebr = 0.0f;
        {
            const float* ew = eps_w + (size_t)t * H * H;
            #pragma unroll
            for (int r = 0; r < 2; r++) {
                int idx = tid * 8 + r * 4;
                int jl = idx >> 9, k = idx & 511;
                er[r] = __ldcs((const float4*)(ew + (size_t)(j0 + jl) * H + k));
            }
            if (tid < 4) ebr = __ldcs(eps_b + (size_t)t * H + j0 + tid);
        }

        // Phase B: layer 1 (writes fp32 timestep output)
        float* out_t = out + (size_t)t * BH;
        lstm_phase_mma(smem, 1, g_h0hi[pong], g_h0lo[pong], g_h1hi[ping], g_h1lo[ping],
                       bsum1, c1r, g_h1hi[pong], g_h1lo[pong], out_t, u0);
        tgt += NBLK; grid_bar(tgt);

        // Phase C: bayes x_next = h1 @ (mu + sig*eps)^T + b_t  (FFMA2, fp32)
        {
            #pragma unroll
            for (int r = 0; r < 2; r++) {
                int idx = tid * 8 + r * 4;
                float4 m = *(const float4*)(mu_s + idx);
                float4 s = *(const float4*)(sig_s + idx);
                float4 e = er[r];
                float4 w;
                w.x = m.x + s.x * e.x; w.y = m.y + s.y * e.y;
                w.z = m.z + s.z * e.z; w.w = m.w + s.w * e.w;
                *(float4*)(Wb + idx) = w;
            }
            if (tid < 4) bb[tid] = bmu_s[tid] + bsg_s[tid] * ebr;

            const int kl = tid & 31;
            const int b0 = (tid >> 5) * 8;
            unsigned long long acc[8][4];
            #pragma unroll
            for (int i = 0; i < 8; i++)
                #pragma unroll
                for (int j = 0; j < 4; j++) acc[i][j] = 0ull;

            for (int ch = 0; ch < 4; ch++) {
                __syncthreads();
                #pragma unroll
                for (int j = 0; j < 8; j++) {
                    int fi = tid + j * NTHR;
                    int b = fi >> 5, kq = fi & 31;
                    *(float4*)(Hs + b * 128 + kq * 4) =
                        __ldcg((const float4*)(out_t + b * H + ch * 128 + kq * 4));
                }
                __syncthreads();
                ulonglong2 hv[8];
                #pragma unroll
                for (int i = 0; i < 8; i++)
                    hv[i] = *(const ulonglong2*)(Hs + (b0 + i) * 128 + kl * 4);
                #pragma unroll
                for (int j = 0; j < 4; j++) {
                    ulonglong2 wv = *(const ulonglong2*)(Wb + j * H + ch * 128 + kl * 4);
                    #pragma unroll
                    for (int i = 0; i < 8; i++) {
                        FMA2(acc[i][j], hv[i].x, wv.x);
                        FMA2(acc[i][j], hv[i].y, wv.y);
                    }
                }
            }
            #pragma unroll
            for (int i = 0; i < 8; i++)
                #pragma unroll
                for (int j = 0; j < 4; j++) {
                    unsigned long long v = acc[i][j], o;
                    o = __shfl_down_sync(0xffffffffu, v, 16); ADD2(v, o);
                    o = __shfl_down_sync(0xffffffffu, v, 8);  ADD2(v, o);
                    o = __shfl_down_sync(0xffffffffu, v, 4);  ADD2(v, o);
                    o = __shfl_down_sync(0xffffffffu, v, 2);  ADD2(v, o);
                    o = __shfl_down_sync(0xffffffffu, v, 1);  ADD2(v, o);
                    if (kl == 0) {
                        float lo, hi; unpack2(v, lo, hi);
                        float xv = lo + hi + bb[j];
                        int idx = (b0 + i) * H + j0 + j;
                        split_store(xv, g_xhi + idx, g_xlo + idx);
                    }
                }
        }
        tgt += NBLK; grid_bar(tgt);
    }
}

// ---------------- launcher ----------------
extern "C" void kernel_launch(void* const* d_in, const int* in_sizes, int n_in,
                              void* d_out, int out_size) {
    const float* init_h = (const float*)d_in[1];
    const float* init_c = (const float*)d_in[2];
    const float* eps_w  = (const float*)d_in[3];
    const float* eps_b  = (const float*)d_in[4];
    const float* W_ih0  = (const float*)d_in[5];
    const float* W_hh0  = (const float*)d_in[6];
    const float* b_ih0  = (const float*)d_in[7];
    const float* b_hh0  = (const float*)d_in[8];
    const float* W_ih1  = (const float*)d_in[9];
    const float* W_hh1  = (const float*)d_in[10];
    const float* b_ih1  = (const float*)d_in[11];
    const float* b_hh1  = (const float*)d_in[12];
    const float* w_mu   = (const float*)d_in[13];
    const float* w_lv   = (const float*)d_in[14];
    const float* b_mu   = (const float*)d_in[15];
    const float* b_lv   = (const float*)d_in[16];
    float* out = (float*)d_out;

    cudaFuncSetAttribute((const void*)dlstm_persistent,
                         cudaFuncAttributeMaxDynamicSharedMemorySize, SMEM_BYTES);

    reset_kernel<<<1, 1>>>();
    dlstm_persistent<<<NBLK, NTHR, SMEM_BYTES>>>(
        init_h, init_c, eps_w, eps_b,
        W_ih0, W_hh0, b_ih0, b_hh0,
        W_ih1, W_hh1, b_ih1, b_hh1,
        w_mu, w_lv, b_mu, b_lv, out);
}